// round 2
// baseline (speedup 1.0000x reference)
#include <cuda_runtime.h>
#include <cstdint>

#define NV_P   32
#define C_VX   0.16f
#define C_VY   0.16f
#define C_VZ   4.0f
#define C_XOFF 0.08f
#define C_YOFF -39.6f
#define C_ZOFF -1.0f
#define BN_EPS 1e-3f

// Global scratch (allocation-free rule: __device__ globals)
__device__ double g_m[10];
__device__ double g_S[55];
__device__ float  g_ab[128];   // a[0..63], b[64..127]

// ---------------- packed f32x2 helpers ----------------
__device__ __forceinline__ unsigned long long pk2(float lo, float hi) {
    unsigned long long r;
    asm("mov.b64 %0, {%1, %2};" : "=l"(r) : "f"(lo), "f"(hi));
    return r;
}
__device__ __forceinline__ void unpk2(unsigned long long x, float& lo, float& hi) {
    asm("mov.b64 {%0, %1}, %2;" : "=f"(lo), "=f"(hi) : "l"(x));
}
__device__ __forceinline__ unsigned long long fma2(unsigned long long a, unsigned long long b, unsigned long long c) {
    unsigned long long d;
    asm("fma.rn.f32x2 %0, %1, %2, %3;" : "=l"(d) : "l"(a), "l"(b), "l"(c));
    return d;
}
__device__ __forceinline__ unsigned long long add2(unsigned long long a, unsigned long long b) {
    unsigned long long d;
    asm("add.rn.f32x2 %0, %1, %2;" : "=l"(d) : "l"(a), "l"(b));
    return d;
}
__device__ __forceinline__ unsigned long long mul2(unsigned long long a, unsigned long long b) {
    unsigned long long d;
    asm("mul.rn.f32x2 %0, %1, %2;" : "=l"(d) : "l"(a), "l"(b));
    return d;
}

__device__ __forceinline__ void wred3(float& a, float& b, float& c) {
#pragma unroll
    for (int off = 16; off; off >>= 1) {
        a += __shfl_xor_sync(0xffffffffu, a, off);
        b += __shfl_xor_sync(0xffffffffu, b, off);
        c += __shfl_xor_sync(0xffffffffu, c, off);
    }
}

// ---------------- k0: zero stats ----------------
__global__ void k0_zero() {
    int t = threadIdx.x;
    if (t < 10) g_m[t] = 0.0;
    if (t < 55) g_S[t] = 0.0;
}

// ---------------- k1: feature moments (m[10], S[55]) ----------------
__global__ __launch_bounds__(256) void k1_stats(
    const float* __restrict__ vf, const int* __restrict__ vnp,
    const int* __restrict__ coords, int V)
{
    float m[10], S[55];
#pragma unroll
    for (int i = 0; i < 10; i++) m[i] = 0.f;
#pragma unroll
    for (int i = 0; i < 55; i++) S[i] = 0.f;

    const int lane = threadIdx.x & 31;
    const int wib  = threadIdx.x >> 5;
    const int gw   = (blockIdx.x * blockDim.x + threadIdx.x) >> 5;
    const int nw   = (gridDim.x * blockDim.x) >> 5;

    int v = gw;
    float4 pt; int cnt; int4 c4;
    if (v < V) {
        pt  = reinterpret_cast<const float4*>(vf)[v * NV_P + lane];
        cnt = vnp[v];
        c4  = reinterpret_cast<const int4*>(coords)[v];
    }
    while (v < V) {
        int vn = v + nw;
        float4 ptn; int cntn; int4 c4n;
        if (vn < V) {   // prefetch next voxel
            ptn  = reinterpret_cast<const float4*>(vf)[vn * NV_P + lane];
            cntn = vnp[vn];
            c4n  = reinterpret_cast<const int4*>(coords)[vn];
        }

        float sx = pt.x, sy = pt.y, sz = pt.z;
        wred3(sx, sy, sz);                    // sum over ALL 32 points (matches ref)
        float inv = 1.0f / (float)cnt;
        float mx = sx * inv, my = sy * inv, mz = sz * inv;
        float cx = (float)c4.w * C_VX + C_XOFF;
        float cy = (float)c4.z * C_VY + C_YOFF;
        float cz = (float)c4.y * C_VZ + C_ZOFF;

        if (lane < cnt) {
            float f[10];
            f[0] = pt.x; f[1] = pt.y; f[2] = pt.z; f[3] = pt.w;
            f[4] = pt.x - mx; f[5] = pt.y - my; f[6] = pt.z - mz;
            f[7] = pt.x - cx; f[8] = pt.y - cy; f[9] = pt.z - cz;
#pragma unroll
            for (int i = 0; i < 10; i++) m[i] += f[i];
            int t = 0;
#pragma unroll
            for (int i = 0; i < 10; i++) {
#pragma unroll
                for (int j = i; j < 10; j++) { S[t] = fmaf(f[i], f[j], S[t]); t++; }
            }
        }
        v = vn; pt = ptn; cnt = cntn; c4 = c4n;
    }

    // warp reduce all 65 accumulators
#pragma unroll
    for (int i = 0; i < 10; i++)
#pragma unroll
        for (int off = 16; off; off >>= 1) m[i] += __shfl_xor_sync(0xffffffffu, m[i], off);
#pragma unroll
    for (int i = 0; i < 55; i++)
#pragma unroll
        for (int off = 16; off; off >>= 1) S[i] += __shfl_xor_sync(0xffffffffu, S[i], off);

    __shared__ float red[65 * 8];
    if (lane == 0) {
#pragma unroll
        for (int i = 0; i < 10; i++) red[i * 8 + wib] = m[i];
#pragma unroll
        for (int i = 0; i < 55; i++) red[(10 + i) * 8 + wib] = S[i];
    }
    __syncthreads();
    int t = threadIdx.x;
    if (t < 65) {
        float s = 0.f;
#pragma unroll
        for (int w = 0; w < 8; w++) s += red[t * 8 + w];
        if (t < 10) atomicAdd(&g_m[t], (double)s);
        else        atomicAdd(&g_S[t - 10], (double)s);
    }
}

// ---------------- k2: fold BN into per-channel a,b ----------------
__global__ void k2_coef(const float* __restrict__ W, const float* __restrict__ gamma,
                        const float* __restrict__ beta, double invN)
{
    int o = threadIdx.x;
    if (o >= 64) return;
    double w[10];
#pragma unroll
    for (int c = 0; c < 10; c++) w[c] = (double)W[o * 10 + c];
    double mean = 0.0;
#pragma unroll
    for (int c = 0; c < 10; c++) mean += w[c] * g_m[c];
    mean *= invN;
    double e2 = 0.0;
    int t = 0;
#pragma unroll
    for (int i = 0; i < 10; i++) {
#pragma unroll
        for (int j = i; j < 10; j++) {
            double coef = (i == j) ? 1.0 : 2.0;
            e2 += coef * w[i] * w[j] * g_S[t]; t++;
        }
    }
    e2 *= invN;
    double var = e2 - mean * mean;
    float a = gamma[o] * rsqrtf((float)var + BN_EPS);
    float b = beta[o] - (float)mean * a;
    g_ab[o]      = a;
    g_ab[64 + o] = b;
}

// ---------------- k3: per-voxel max/min of x, then relu(a*sel+b) ----------------
__global__ __launch_bounds__(256) void k3_out(
    const float* __restrict__ vf, const int* __restrict__ vnp,
    const int* __restrict__ coords, const float* __restrict__ W,
    float* __restrict__ out, int V)
{
    __shared__ __align__(16) float sh[8 * NV_P * 8];   // 8 warps * 32 pts * 8 floats
    const int lane = threadIdx.x & 31;
    const int wib  = threadIdx.x >> 5;
    const int gw   = (blockIdx.x * blockDim.x + threadIdx.x) >> 5;
    const int nw   = (gridDim.x * blockDim.x) >> 5;
    float* msh = sh + wib * (NV_P * 8);

    // lane owns output channels (2*lane, 2*lane+1); weights packed f32x2
    unsigned long long wp[10];
#pragma unroll
    for (int c = 0; c < 10; c++)
        wp[c] = pk2(W[(2 * lane) * 10 + c], W[(2 * lane + 1) * 10 + c]);
    unsigned long long u0 = add2(add2(wp[0], wp[4]), wp[7]);
    unsigned long long u1 = add2(add2(wp[1], wp[5]), wp[8]);
    unsigned long long u2 = add2(add2(wp[2], wp[6]), wp[9]);
    unsigned long long u3 = wp[3];

    float2 av = reinterpret_cast<const float2*>(g_ab)[lane];
    float2 bv = reinterpret_cast<const float2*>(g_ab + 64)[lane];

    int v = gw;
    float4 pt; int cnt; int4 c4;
    if (v < V) {
        pt  = reinterpret_cast<const float4*>(vf)[v * NV_P + lane];
        cnt = vnp[v];
        c4  = reinterpret_cast<const int4*>(coords)[v];
    }
    while (v < V) {
        int vn = v + nw;
        float4 ptn; int cntn; int4 c4n;
        if (vn < V) {   // prefetch
            ptn  = reinterpret_cast<const float4*>(vf)[vn * NV_P + lane];
            cntn = vnp[vn];
            c4n  = reinterpret_cast<const int4*>(coords)[vn];
        }

        float sx = pt.x, sy = pt.y, sz = pt.z;
        wred3(sx, sy, sz);
        float inv = 1.0f / (float)cnt;
        float nmx = -(sx * inv), nmy = -(sy * inv), nmz = -(sz * inv);
        float ncx = -((float)c4.w * C_VX + C_XOFF);
        float ncy = -((float)c4.z * C_VY + C_YOFF);
        float ncz = -((float)c4.y * C_VZ + C_ZOFF);
        // base = -(m . w[4:7] + c . w[7:10]) per channel pair
        unsigned long long base = mul2(pk2(nmx, nmx), wp[4]);
        base = fma2(pk2(nmy, nmy), wp[5], base);
        base = fma2(pk2(nmz, nmz), wp[6], base);
        base = fma2(pk2(ncx, ncx), wp[7], base);
        base = fma2(pk2(ncy, ncy), wp[8], base);
        base = fma2(pk2(ncz, ncz), wp[9], base);

        // stage duplicated point data: (x,x,y,y,z,z,w,w) -> LDS.128 gives f32x2 pairs
        __syncwarp();
        float4* sp = reinterpret_cast<float4*>(msh + lane * 8);
        sp[0] = make_float4(pt.x, pt.x, pt.y, pt.y);
        sp[1] = make_float4(pt.z, pt.z, pt.w, pt.w);
        __syncwarp();

        float maxlo, maxhi, minlo, minhi;
        if (cnt < NV_P) { maxlo = maxhi = 0.f;              minlo = minhi = 0.f; }
        else            { maxlo = maxhi = -3.402823466e38f; minlo = minhi = 3.402823466e38f; }

        const ulonglong2* pp = reinterpret_cast<const ulonglong2*>(msh);
        for (int p = 0; p < cnt; p++) {
            ulonglong2 q = pp[2 * p];       // (x,x),(y,y)
            ulonglong2 r = pp[2 * p + 1];   // (z,z),(w,w)
            unsigned long long acc = fma2(q.x, u0, base);
            acc = fma2(q.y, u1, acc);
            acc = fma2(r.x, u2, acc);
            acc = fma2(r.y, u3, acc);
            float xlo, xhi; unpk2(acc, xlo, xhi);
            maxlo = fmaxf(maxlo, xlo); maxhi = fmaxf(maxhi, xhi);
            minlo = fminf(minlo, xlo); minhi = fminf(minhi, xhi);
        }
        float s0 = (av.x >= 0.f) ? maxlo : minlo;
        float s1 = (av.y >= 0.f) ? maxhi : minhi;
        float r0 = fmaxf(fmaf(av.x, s0, bv.x), 0.f);
        float r1 = fmaxf(fmaf(av.y, s1, bv.y), 0.f);
        reinterpret_cast<float2*>(out)[v * 32 + lane] = make_float2(r0, r1);

        v = vn; pt = ptn; cnt = cntn; c4 = c4n;
    }
}

extern "C" void kernel_launch(void* const* d_in, const int* in_sizes, int n_in,
                              void* d_out, int out_size) {
    const float* vf     = (const float*)d_in[0];
    const int*   vnp    = (const int*)d_in[1];
    const int*   coords = (const int*)d_in[2];
    const float* W      = (const float*)d_in[3];
    const float* gamma  = (const float*)d_in[4];
    const float* beta   = (const float*)d_in[5];
    float* out = (float*)d_out;
    int V = in_sizes[1];   // voxel_num_points element count

    k0_zero<<<1, 64>>>();
    k1_stats<<<592, 256>>>(vf, vnp, coords, V);
    double invN = 1.0 / ((double)V * (double)NV_P);
    k2_coef<<<1, 64>>>(W, gamma, beta, invN);
    k3_out<<<888, 256>>>(vf, vnp, coords, W, out, V);
}